// round 16
// baseline (speedup 1.0000x reference)
#include <cuda_runtime.h>
#include <cuda_bf16.h>

// MedianFilter1D: k=9 sliding median, replicate padding. x: [2048 rows, 8192] fp32.
//
// R16: barrier-domain de-phasing at constant warp count. NT=128, quarter-row
// tiles (2048 outputs, 8.2KB smem), __launch_bounds__(128,10): 40 warps/SM
// (same as R9's occ-5 x 256thr) but 10 INDEPENDENT barrier domains instead
// of 5 — a CTA stalled in its load->barrier window idles 4 warps, not 8,
// and the other 9 domains keep the issue slots fed. vs failed R3: 10 domains
// (not 6), ITERS=4 (not 2; prologue 25% of instr), dual-pipe R9 math.

#define ROW_L 8192
#define TILE  2048
#define TPR   (ROW_L / TILE)         // 4 tiles per row
#define PAD   4
#define NT    128
#define ITERS (TILE / 4 / NT)        // 4 quads per thread

// ---- FMA-pipe compare-swap (sum/|diff| trick, <=1ulp; validated R9+). ----
__device__ __forceinline__ void cswap_fma(float& a, float& b) {
    float s  = a + b;
    float d  = a - b;
    float ad = fabsf(d);
    float lo = (s - ad) * 0.5f;
    float hi = (s + ad) * 0.5f;
    a = lo; b = hi;
}
__device__ __forceinline__ void sort3_fma(float& a, float& b, float& c) {
    cswap_fma(a, b);
    cswap_fma(b, c);
    cswap_fma(a, b);
}

// ---- ALU-pipe (FMNMX) helpers. ----
__device__ __forceinline__ float med3(float a, float b, float c) {
    return fmaxf(fminf(a, b), fminf(fmaxf(a, b), c));
}
__device__ __forceinline__ float median_out(float x, float p0, float p1,
                                            float mm, float nn,
                                            float p, float qp1) {
    float a0 = fminf(x, p0);
    float m  = fmaxf(x, p0);
    float lo  = fmaxf(a0, mm);
    float mid = fmaxf(p, fminf(qp1, m));
    float hi  = fminf(fmaxf(m, p1), nn);
    return med3(lo, mid, hi);
}

// 4 outputs from 12 consecutive values (identity validated R2..R15).
__device__ __forceinline__ float4 median4(float4 va, float4 vb, float4 vc) {
    float b0 = va.w, b1 = vb.x, b2 = vb.y; sort3_fma(b0, b1, b2);  // T1
    float c0 = vb.z, c1 = vb.w, c2 = vc.x; sort3_fma(c0, c1, c2);  // T2
    float s1 = va.y, s2 = va.z; cswap_fma(s1, s2);                 // (v1,v2)
    float t1 = vc.y, t2 = vc.z; cswap_fma(t1, t2);                 // (v9,v10)
    const float mm  = fmaxf(b0, c0);
    const float nn  = fminf(b2, c2);
    const float p   = fminf(b1, c1);
    const float q   = fmaxf(b1, c1);
    const float qs2 = fminf(q, s2);
    const float qt2 = fminf(q, t2);
    float4 r;
    r.x = median_out(va.x, s1, s2, mm, nn, p, qs2);
    r.y = median_out(vc.y, s1, s2, mm, nn, p, qs2);
    r.z = median_out(va.z, t1, t2, mm, nn, p, qt2);
    r.w = median_out(vc.w, t1, t2, mm, nn, p, qt2);
    return r;
}

__global__ __launch_bounds__(NT, 10)
void median9_kernel(const float* __restrict__ x, float* __restrict__ y) {
    __shared__ __align__(16) float s[TILE + 2 * PAD];

    const int row  = blockIdx.x >> 2;            // / TPR
    const int tb   = (blockIdx.x & (TPR - 1)) * TILE;  // tile base in row
    const float* __restrict__ xr = x + ((size_t)row << 13);
    float* __restrict__ yo       = y + ((size_t)row << 13) + tb;
    const int t = threadIdx.x;

    // ---- Stage tile into smem: s[PAD + i] = xr[tb + i] (float4, coalesced).
    const float4* x4 = (const float4*)(xr + tb);
    #pragma unroll
    for (int j = 0; j < ITERS; j++) {
        int i = t + NT * j;                      // float4 index 0..511
        *(float4*)&s[PAD + 4 * i] = x4[i];
    }
    // Halos: clamped global loads (real neighbors at interior tile seams,
    // replicate at true row edges). 8 scalar LDGs per CTA.
    if (t < 2 * PAD) {
        int k  = (t < PAD) ? t : (PAD + TILE + (t - PAD));
        int gi = tb - PAD + ((t < PAD) ? t : (PAD + (t - PAD) + TILE - PAD + PAD));
        gi = tb - PAD + k;                       // global idx of s[k]
        gi = min(max(gi, 0), ROW_L - 1);
        s[k] = xr[gi];
    }
    __syncthreads();

    // ---- 4 quads per thread, 16B lane stride (conflict-free LDS). ----
    #pragma unroll
    for (int u = 0; u < ITERS; u++) {
        const int o = 4 * t + 4 * NT * u;        // tile-local quad base
        float4 va = *(const float4*)&s[o];
        float4 vb = *(const float4*)&s[o + 4];
        float4 vc = *(const float4*)&s[o + 8];
        *(float4*)(yo + o) = median4(va, vb, vc);
    }
}

extern "C" void kernel_launch(void* const* d_in, const int* in_sizes, int n_in,
                              void* d_out, int out_size) {
    const float* x = (const float*)d_in[0];
    float* y = (float*)d_out;
    const int rows = in_sizes[0] / ROW_L;        // B*C = 2048
    median9_kernel<<<rows * TPR, NT>>>(x, y);    // 8192 CTAs x 128 thr
}